// round 14
// baseline (speedup 1.0000x reference)
#include <cuda_runtime.h>
#include <cuda_fp16.h>
#include <cstdint>

#define SQ 2048
#define DM 1024
#define NH 8

// ---------------------------------------------------------------------------
// Scratch (device globals; no allocation allowed). All operands pre-split
// into fp16 hi/lo pairs; logits stay fp32 (magnitude ~1000 needs fp32).
// ---------------------------------------------------------------------------
__device__ __half g_hidden_h[(long)SQ * DM],  g_hidden_l[(long)SQ * DM];
__device__ __half g_rel_h[(long)SQ * DM],     g_rel_l[(long)SQ * DM];
__device__ __half g_x_h[(long)SQ * DM],       g_x_l[(long)SQ * DM];
__device__ __half g_xT_h[(long)DM * SQ],      g_xT_l[(long)DM * SQ];
__device__ __half g_scores_h[(long)NH * SQ * DM], g_scores_l[(long)NH * SQ * DM];
__device__ float  g_logits[(long)NH * SQ * SQ];
__device__ __half g_attn_h[(long)NH * SQ * SQ],   g_attn_l[(long)NH * SQ * SQ];
__device__ __half g_context_h[(long)SQ * NH * DM], g_context_l[(long)SQ * NH * DM];
__device__ __half g_rew2T_h[(long)DM * DM],   g_rew2T_l[(long)DM * DM];
__device__ __half g_attnwT_h[(long)NH * DM * DM], g_attnwT_l[(long)NH * DM * DM];
__device__ __half g_outwT_h[(long)DM * NH * DM],  g_outwT_l[(long)DM * NH * DM];
__device__ float  g_part[(long)4 * SQ * DM];   // 32 MB split-K partials (GEMM7)

// ---------------------------------------------------------------------------
// helpers
// ---------------------------------------------------------------------------
__device__ __forceinline__ uint32_t pack_f16(float lo, float hi) {
    uint32_t w;
    asm("cvt.rn.f16x2.f32 %0, %1, %2;" : "=r"(w) : "f"(hi), "f"(lo));
    return w;
}
__device__ __forceinline__ void unpack_f16(uint32_t w, float& lo, float& hi) {
    __half2 h = *(__half2*)&w;
    lo = __low2float(h);
    hi = __high2float(h);
}
__device__ __forceinline__ void mma_f16(float c[4], const uint32_t a[4], const uint32_t b[2]) {
    asm volatile(
        "mma.sync.aligned.m16n8k16.row.col.f32.f16.f16.f32 "
        "{%0,%1,%2,%3}, {%4,%5,%6,%7}, {%8,%9}, {%0,%1,%2,%3};\n"
        : "+f"(c[0]), "+f"(c[1]), "+f"(c[2]), "+f"(c[3])
        : "r"(a[0]), "r"(a[1]), "r"(a[2]), "r"(a[3]), "r"(b[0]), "r"(b[1]));
}
__device__ __forceinline__ void ldsm4(uint32_t f[4], uint32_t addr) {
    asm volatile("ldmatrix.sync.aligned.m8n8.x4.shared.b16 {%0,%1,%2,%3}, [%4];"
                 : "=r"(f[0]), "=r"(f[1]), "=r"(f[2]), "=r"(f[3]) : "r"(addr));
}
__device__ __forceinline__ void cp16(uint32_t dst, const void* src) {
    asm volatile("cp.async.cg.shared.global [%0], [%1], 16;" :: "r"(dst), "l"(src));
}
__device__ __forceinline__ void cp_commit() {
    asm volatile("cp.async.commit_group;" ::: "memory");
}
template <int N>
__device__ __forceinline__ void cp_wait() {
    asm volatile("cp.async.wait_group %0;" :: "n"(N) : "memory");
}

// ---------------------------------------------------------------------------
// producers
// ---------------------------------------------------------------------------
__global__ void split_kernel(const float* __restrict__ in,
                             __half* __restrict__ oh, __half* __restrict__ ol)
{
    int idx = blockIdx.x * blockDim.x + threadIdx.x;
    float v = in[idx];
    __half h = __float2half_rn(v);
    oh[idx] = h;
    ol[idx] = __float2half_rn(v - __half2float(h));
}

__global__ void transpose_split_kernel(const float* __restrict__ in,
                                       __half* __restrict__ oh, __half* __restrict__ ol,
                                       int R, int C, long long sIn, long long sOut)
{
    __shared__ float t[32][33];
    in += (long long)blockIdx.z * sIn;
    oh += (long long)blockIdx.z * sOut;
    ol += (long long)blockIdx.z * sOut;
    int r0 = blockIdx.y * 32, c0 = blockIdx.x * 32;
    int tx = threadIdx.x, ty = threadIdx.y;
#pragma unroll
    for (int i = 0; i < 4; i++)
        t[ty + 8 * i][tx] = in[(long long)(r0 + ty + 8 * i) * C + c0 + tx];
    __syncthreads();
#pragma unroll
    for (int i = 0; i < 4; i++) {
        float v = t[tx][ty + 8 * i];
        __half h = __float2half_rn(v);
        long long o = (long long)(c0 + ty + 8 * i) * R + r0 + tx;
        oh[o] = h;
        ol[o] = __float2half_rn(v - __half2float(h));
    }
}

__global__ void rel_hidden_kernel(const float* __restrict__ relations,
                                  const float* __restrict__ w1,
                                  const float* __restrict__ b1,
                                  __half* __restrict__ oh, __half* __restrict__ ol)
{
    int idx = blockIdx.x * blockDim.x + threadIdx.x;
    int s = idx >> 10;
    int d = idx & (DM - 1);
    float v = b1[d];
    v = fmaf(relations[s * 4 + 0], w1[0 * DM + d], v);
    v = fmaf(relations[s * 4 + 1], w1[1 * DM + d], v);
    v = fmaf(relations[s * 4 + 2], w1[2 * DM + d], v);
    v = fmaf(relations[s * 4 + 3], w1[3 * DM + d], v);
    v = fmaxf(v, 0.0f);
    __half h = __float2half_rn(v);
    oh[idx] = h;
    ol[idx] = __float2half_rn(v - __half2float(h));
}

// split-K reduction for GEMM7: out = sum of 4 partials + bias
__global__ void reduce4_kernel(const float* __restrict__ part,
                               const float* __restrict__ bias,
                               float* __restrict__ out)
{
    int i = blockIdx.x * 256 + threadIdx.x;       // over SQ*DM/4 float4s
    const long long P = (long long)SQ * DM;
    float4 a = *(const float4*)&part[(long long)i * 4];
    float4 b = *(const float4*)&part[P + (long long)i * 4];
    float4 c = *(const float4*)&part[2 * P + (long long)i * 4];
    float4 d = *(const float4*)&part[3 * P + (long long)i * 4];
    int col = (i * 4) & (DM - 1);
    float4 bb = *(const float4*)&bias[col];
    float4 o;
    o.x = a.x + b.x + c.x + d.x + bb.x;
    o.y = a.y + b.y + c.y + d.y + bb.y;
    o.z = a.z + b.z + c.z + d.z + bb.z;
    o.w = a.w + b.w + c.w + d.w + bb.w;
    *(float4*)&out[(long long)i * 4] = o;
}

// ---------------------------------------------------------------------------
// Pre-split fp16 3-term NT GEMM, templated on BN (128 or 256):
//   C[M,N] = (Ah+Al)[M,K] @ (Bh+Bl)[N,K]^T    terms: Ah*Bl + Ah*Bh + Al*Bh
// CTA tile 128 x BN, BK=32, 2*BN threads, warp tile 64x32 (m-warps x n-warps).
// smem stage = AH|AL (128x80B) + BH|BL (BNx80B), cp.async coalesced
// (row-contiguous), fragments via ldmatrix.x4 (conflict-free @ 80B stride).
// 1 __syncthreads per mainloop iteration (wait -> sync -> load next -> compute).
// EPI_SPLIT=1: C written as fp16 h/l pair (+bias). 0: fp32 (+bias).
// ---------------------------------------------------------------------------
template <int BN, int EPI_SPLIT>
__global__ __launch_bounds__(BN * 2, BN == 128 ? 2 : 1)
void gemm_pre(const __half* __restrict__ Ah, const __half* __restrict__ Al,
              const __half* __restrict__ Bh, const __half* __restrict__ Bl,
              float* __restrict__ Cf, __half* __restrict__ Ch, __half* __restrict__ Cl,
              const float* __restrict__ bias,
              int K, int lda, int ldb, int ldc,
              long long sAb, long long sBb, long long sCb)
{
    constexpr int THREADS = BN * 2;
    constexpr int TILE_A  = 10240;            // 128 * 80 B
    constexpr int TILE_BB = BN * 80;          // B tile bytes
    constexpr int OFF_AL  = TILE_A;
    constexpr int OFF_BH  = 2 * TILE_A;
    constexpr int OFF_BL  = 2 * TILE_A + TILE_BB;
    constexpr int STAGE   = 2 * TILE_A + 2 * TILE_BB;
    constexpr int CHUNKS  = 1024 + 8 * BN;    // 16B chunks per stage
    constexpr int CPT     = CHUNKS / THREADS; // per thread

    extern __shared__ char sm[];
    const uint32_t sbase = (uint32_t)__cvta_generic_to_shared(sm);

    const int tid  = threadIdx.x;
    const int lane = tid & 31;
    const int w    = tid >> 5;
    const int q    = lane >> 2;
    const int r    = lane & 3;
    const int wm   = (w & 1) * 64;
    const int wn   = (w >> 1) * 32;

    const long long z = blockIdx.z;
    Ah += z * sAb;  Al += z * sAb;
    Bh += z * sBb;  Bl += z * sBb;
    if (EPI_SPLIT) { Ch += z * sCb; Cl += z * sCb; }
    else           { Cf += z * sCb; }
    const int bm = blockIdx.y * 128;
    const int bn = blockIdx.x * BN;

    // ldmatrix per-lane fragment offset (bytes)
    const int r8 = lane & 7, g = lane >> 3;
    const uint32_t frag = (uint32_t)(((r8 + 8 * (g & 1)) * 20 + 4 * (g >> 1)) * 4);
    const uint32_t aoff = frag + (uint32_t)wm * 80;
    const uint32_t boff = frag + (uint32_t)wn * 80;

    auto stage_load = [&](int st, int k0) {
        uint32_t s0 = sbase + st * STAGE;
#pragma unroll
        for (int i = 0; i < CPT; i++) {
            int c = tid + THREADS * i;
            const __half* src;
            int rb, ldv;
            uint32_t tbase;
            int local;
            if (c < 1024) {                       // A tiles: 512 chunks each
                local = c & 511;
                tbase = (c < 512) ? 0u : (uint32_t)OFF_AL;
                src   = (c < 512) ? Ah : Al;
                rb = bm; ldv = lda;
            } else {                              // B tiles: 4*BN chunks each
                int cb = c - 1024;
                bool hi = cb < 4 * BN;
                local = cb & (4 * BN - 1);
                tbase = hi ? (uint32_t)OFF_BH : (uint32_t)OFF_BL;
                src   = hi ? Bh : Bl;
                rb = bn; ldv = ldb;
            }
            int row = local >> 2, seg = local & 3;
            cp16(s0 + tbase + row * 80 + seg * 16,
                 src + (long long)(rb + row) * ldv + k0 + seg * 8);
        }
    };

    float acc[4][4][4] = {};

    auto compute = [&](int st) {
        uint32_t s0 = sbase + st * STAGE;
#pragma unroll
        for (int k16 = 0; k16 < 2; k16++) {
            const uint32_t ko = k16 * 32;
            uint32_t af[4][4], bp[2][4];
            // term 1: Ah * Bl
#pragma unroll
            for (int mi = 0; mi < 4; mi++) ldsm4(af[mi], s0 + aoff + mi * 1280 + ko);
#pragma unroll
            for (int p = 0; p < 2; p++)    ldsm4(bp[p], s0 + OFF_BL + boff + p * 1280 + ko);
#pragma unroll
            for (int mi = 0; mi < 4; mi++)
#pragma unroll
                for (int ni = 0; ni < 4; ni++) {
                    uint32_t b2[2] = { bp[ni >> 1][ni & 1], bp[ni >> 1][2 + (ni & 1)] };
                    mma_f16(acc[mi][ni], af[mi], b2);
                }
            // term 2: Ah * Bh (reuse af)
#pragma unroll
            for (int p = 0; p < 2; p++)    ldsm4(bp[p], s0 + OFF_BH + boff + p * 1280 + ko);
#pragma unroll
            for (int mi = 0; mi < 4; mi++)
#pragma unroll
                for (int ni = 0; ni < 4; ni++) {
                    uint32_t b2[2] = { bp[ni >> 1][ni & 1], bp[ni >> 1][2 + (ni & 1)] };
                    mma_f16(acc[mi][ni], af[mi], b2);
                }
            // term 3: Al * Bh (reuse bp)
#pragma unroll
            for (int mi = 0; mi < 4; mi++) ldsm4(af[mi], s0 + OFF_AL + aoff + mi * 1280 + ko);
#pragma unroll
            for (int mi = 0; mi < 4; mi++)
#pragma unroll
                for (int ni = 0; ni < 4; ni++) {
                    uint32_t b2[2] = { bp[ni >> 1][ni & 1], bp[ni >> 1][2 + (ni & 1)] };
                    mma_f16(acc[mi][ni], af[mi], b2);
                }
        }
    };

    const int iters = K >> 5;

    stage_load(0, 0);
    cp_commit();

    for (int it = 0; it < iters; ++it) {
        cp_wait<0>();
        __syncthreads();          // stage it ready + prior compute finished
        if (it + 1 < iters) {
            stage_load((it + 1) & 1, (it + 1) << 5);
            cp_commit();
        }
        compute(it & 1);
    }

    // ---- epilogue ----------------------------------------------------------
#pragma unroll
    for (int mi = 0; mi < 4; mi++) {
#pragma unroll
        for (int ni = 0; ni < 4; ni++) {
            int row = bm + wm + mi * 16 + q;
            int col = bn + wn + ni * 8 + 2 * r;
            float c0 = acc[mi][ni][0], c1 = acc[mi][ni][1];
            float c2 = acc[mi][ni][2], c3 = acc[mi][ni][3];
            if (bias) {
                float2 bb = *(const float2*)&bias[col];
                c0 += bb.x; c1 += bb.y;
                c2 += bb.x; c3 += bb.y;
            }
            if (EPI_SPLIT) {
                long long o0 = ((long long)row * ldc + col) >> 1;
                long long o1 = ((long long)(row + 8) * ldc + col) >> 1;
                uint32_t hw0 = pack_f16(c0, c1);
                float h0, h1; unpack_f16(hw0, h0, h1);
                ((uint32_t*)Ch)[o0] = hw0;
                ((uint32_t*)Cl)[o0] = pack_f16(c0 - h0, c1 - h1);
                uint32_t hw1 = pack_f16(c2, c3);
                unpack_f16(hw1, h0, h1);
                ((uint32_t*)Ch)[o1] = hw1;
                ((uint32_t*)Cl)[o1] = pack_f16(c2 - h0, c3 - h1);
            } else {
                *(float2*)&Cf[(long long)row * ldc + col]       = make_float2(c0, c1);
                *(float2*)&Cf[(long long)(row + 8) * ldc + col] = make_float2(c2, c3);
            }
        }
    }
}

// ---------------------------------------------------------------------------
// Softmax over rows of length SQ; reads fp32 logits, writes attn as fp16 h/l.
// ---------------------------------------------------------------------------
__global__ __launch_bounds__(256)
void softmax_split_kernel(const float* __restrict__ logits,
                          __half* __restrict__ ah, __half* __restrict__ al)
{
    const long long rbase = (long long)blockIdx.x * SQ;
    const float* row = logits + rbase;
    const int t = threadIdx.x;
    const int lane = t & 31, w = t >> 5;
    __shared__ float redm[8], reds[8];

    float4 a = *(const float4*)&row[t * 8];
    float4 b = *(const float4*)&row[t * 8 + 4];

    float m = fmaxf(fmaxf(fmaxf(a.x, a.y), fmaxf(a.z, a.w)),
                    fmaxf(fmaxf(b.x, b.y), fmaxf(b.z, b.w)));
#pragma unroll
    for (int o = 16; o > 0; o >>= 1) m = fmaxf(m, __shfl_xor_sync(0xffffffffu, m, o));
    if (lane == 0) redm[w] = m;
    __syncthreads();
    float mm = redm[0];
#pragma unroll
    for (int i = 1; i < 8; i++) mm = fmaxf(mm, redm[i]);

    a.x = __expf(a.x - mm); a.y = __expf(a.y - mm);
    a.z = __expf(a.z - mm); a.w = __expf(a.w - mm);
    b.x = __expf(b.x - mm); b.y = __expf(b.y - mm);
    b.z = __expf(b.z - mm); b.w = __expf(b.w - mm);

    float s = (a.x + a.y) + (a.z + a.w) + (b.x + b.y) + (b.z + b.w);
#pragma unroll
    for (int o = 16; o > 0; o >>= 1) s += __shfl_xor_sync(0xffffffffu, s, o);
    if (lane == 0) reds[w] = s;
    __syncthreads();
    float ss = reds[0];
#pragma unroll
    for (int i = 1; i < 8; i++) ss += reds[i];
    float inv = 1.0f / ss;

    float p[8] = { a.x * inv, a.y * inv, a.z * inv, a.w * inv,
                   b.x * inv, b.y * inv, b.z * inv, b.w * inv };

    uint4 H, L;
    uint32_t* hp = (uint32_t*)&H;
    uint32_t* lp = (uint32_t*)&L;
#pragma unroll
    for (int i = 0; i < 4; i++) {
        uint32_t hw = pack_f16(p[2 * i], p[2 * i + 1]);
        float h0, h1; unpack_f16(hw, h0, h1);
        hp[i] = hw;
        lp[i] = pack_f16(p[2 * i] - h0, p[2 * i + 1] - h1);
    }
    *(uint4*)((uint32_t*)ah + ((rbase + t * 8) >> 1)) = H;
    *(uint4*)((uint32_t*)al + ((rbase + t * 8) >> 1)) = L;
}

// ---------------------------------------------------------------------------
// Launch
// ---------------------------------------------------------------------------
extern "C" void kernel_launch(void* const* d_in, const int* in_sizes, int n_in,
                              void* d_out, int out_size)
{
    const float* x         = (const float*)d_in[0];
    const float* relations = (const float*)d_in[1];
    const float* re_w1     = (const float*)d_in[2];
    const float* re_b1     = (const float*)d_in[3];
    const float* re_w2     = (const float*)d_in[4];
    const float* re_b2     = (const float*)d_in[5];
    const float* attn_w    = (const float*)d_in[6];
    const float* out_w     = (const float*)d_in[7];
    const float* out_b     = (const float*)d_in[8];
    float* out = (float*)d_out;

    __half *hidden_h, *hidden_l, *rel_h, *rel_l, *x_h, *x_l, *xT_h, *xT_l;
    __half *scores_h, *scores_l, *attn_h, *attn_l, *context_h, *context_l;
    __half *rew2T_h, *rew2T_l, *attnwT_h, *attnwT_l, *outwT_h, *outwT_l;
    float *logits, *part;
    cudaGetSymbolAddress((void**)&hidden_h,  g_hidden_h);
    cudaGetSymbolAddress((void**)&hidden_l,  g_hidden_l);
    cudaGetSymbolAddress((void**)&rel_h,     g_rel_h);
    cudaGetSymbolAddress((void**)&rel_l,     g_rel_l);
    cudaGetSymbolAddress((void**)&x_h,       g_x_h);
    cudaGetSymbolAddress((void**)&x_l,       g_x_l);
    cudaGetSymbolAddress((void**)&xT_h,      g_xT_h);
    cudaGetSymbolAddress((void**)&xT_l,      g_xT_l);
    cudaGetSymbolAddress((void**)&scores_h,  g_scores_h);
    cudaGetSymbolAddress((void**)&scores_l,  g_scores_l);
    cudaGetSymbolAddress((void**)&logits,    g_logits);
    cudaGetSymbolAddress((void**)&attn_h,    g_attn_h);
    cudaGetSymbolAddress((void**)&attn_l,    g_attn_l);
    cudaGetSymbolAddress((void**)&context_h, g_context_h);
    cudaGetSymbolAddress((void**)&context_l, g_context_l);
    cudaGetSymbolAddress((void**)&rew2T_h,   g_rew2T_h);
    cudaGetSymbolAddress((void**)&rew2T_l,   g_rew2T_l);
    cudaGetSymbolAddress((void**)&attnwT_h,  g_attnwT_h);
    cudaGetSymbolAddress((void**)&attnwT_l,  g_attnwT_l);
    cudaGetSymbolAddress((void**)&outwT_h,   g_outwT_h);
    cudaGetSymbolAddress((void**)&outwT_l,   g_outwT_l);
    cudaGetSymbolAddress((void**)&part,      g_part);

    const int smem128 = 2 * (2 * 10240 + 2 * 128 * 80);   // 81920
    const int smem256 = 2 * (2 * 10240 + 2 * 256 * 80);   // 122880
    cudaFuncSetAttribute(gemm_pre<128, 1>, cudaFuncAttributeMaxDynamicSharedMemorySize, smem128);
    cudaFuncSetAttribute(gemm_pre<256, 0>, cudaFuncAttributeMaxDynamicSharedMemorySize, smem256);
    cudaFuncSetAttribute(gemm_pre<256, 1>, cudaFuncAttributeMaxDynamicSharedMemorySize, smem256);

    // 0) one-time splits / transposed splits
    transpose_split_kernel<<<dim3(32, 32, 1), dim3(32, 8)>>>(re_w2, rew2T_h, rew2T_l, DM, DM, 0, 0);
    transpose_split_kernel<<<dim3(32, 32, NH), dim3(32, 8)>>>(attn_w, attnwT_h, attnwT_l, DM, DM,
                                                              (long long)DM * DM, (long long)DM * DM);
    transpose_split_kernel<<<dim3(32, 256, 1), dim3(32, 8)>>>(out_w, outwT_h, outwT_l, NH * DM, DM, 0, 0);
    transpose_split_kernel<<<dim3(32, 64, 1), dim3(32, 8)>>>(x, xT_h, xT_l, SQ, DM, 0, 0);
    split_kernel<<<(SQ * DM) / 256, 256>>>(x, x_h, x_l);

    // 1) hidden = relu(relations @ re_w1 + b1), split
    rel_hidden_kernel<<<(SQ * DM) / 256, 256>>>(relations, re_w1, re_b1, hidden_h, hidden_l);

    // 2) rel = hidden @ re_w2 + b2  -> split (BN=128: grid 128 CTAs, 2/SM)
    gemm_pre<128, 1><<<dim3(8, 16, 1), 256, smem128>>>(
        hidden_h, hidden_l, rew2T_h, rew2T_l, nullptr, rel_h, rel_l, re_b2,
        DM, DM, DM, DM, 0, 0, 0);

    // 3) scores[h] = x @ attn_w[h] -> split  (BN=256)
    gemm_pre<256, 1><<<dim3(4, 16, NH), 512, smem256>>>(
        x_h, x_l, attnwT_h, attnwT_l, nullptr, scores_h, scores_l, nullptr,
        DM, DM, DM, DM, 0, (long long)DM * DM, (long long)SQ * DM);

    // 4) logits[h] = rel @ K_h^T -> fp32  (BN=256)
    gemm_pre<256, 0><<<dim3(8, 16, NH), 512, smem256>>>(
        rel_h, rel_l, scores_h, scores_l, logits, nullptr, nullptr, nullptr,
        DM, DM, NH * DM, SQ, 0, (long long)DM, (long long)SQ * SQ);

    // 5) softmax rows, write attn as fp16 h/l
    softmax_split_kernel<<<NH * SQ, 256>>>(logits, attn_h, attn_l);

    // 6) context = attn @ x  (B = x^T) -> split  (BN=256)
    gemm_pre<256, 1><<<dim3(4, 16, NH), 512, smem256>>>(
        attn_h, attn_l, xT_h, xT_l, nullptr, context_h, context_l, nullptr,
        SQ, SQ, SQ, NH * DM, (long long)SQ * SQ, 0, (long long)DM);

    // 7) out = context @ out_w + out_b: split-K=4 (BN=256), partials fp32
    //    slice z: A cols [z*2048, +2048) of context, B cols same of out_wT
    gemm_pre<256, 0><<<dim3(4, 16, 4), 512, smem256>>>(
        context_h, context_l, outwT_h, outwT_l, part, nullptr, nullptr, nullptr,
        SQ, NH * DM, NH * DM, DM,
        (long long)SQ, (long long)SQ, (long long)SQ * DM);
    reduce4_kernel<<<(SQ * DM / 4) / 256, 256>>>(part, out_b, out);

    (void)in_sizes; (void)n_in; (void)out_size;
}

// round 16
// speedup vs baseline: 1.4908x; 1.4908x over previous
#include <cuda_runtime.h>
#include <cuda_fp16.h>
#include <cstdint>

#define SQ 2048
#define DM 1024
#define NH 8

// ---------------------------------------------------------------------------
// Scratch (device globals; no allocation allowed). Operands pre-split into
// fp16 hi/lo pairs; logits fp32; context built by sparse gather (fp32->h/l).
// ---------------------------------------------------------------------------
__device__ __half g_hidden_h[(long)SQ * DM],  g_hidden_l[(long)SQ * DM];
__device__ __half g_rel_h[(long)SQ * DM],     g_rel_l[(long)SQ * DM];
__device__ __half g_x_h[(long)SQ * DM],       g_x_l[(long)SQ * DM];
__device__ __half g_scores_h[(long)NH * SQ * DM], g_scores_l[(long)NH * SQ * DM];
__device__ float  g_logits[(long)NH * SQ * SQ];
__device__ __half g_context_h[(long)SQ * NH * DM], g_context_l[(long)SQ * NH * DM];
__device__ __half g_rew2T_h[(long)DM * DM],   g_rew2T_l[(long)DM * DM];
__device__ __half g_attnwT_h[(long)NH * DM * DM], g_attnwT_l[(long)NH * DM * DM];
__device__ __half g_outwT_h[(long)DM * NH * DM],  g_outwT_l[(long)DM * NH * DM];
__device__ float  g_part[(long)2 * SQ * DM];   // split-K partials (GEMM7)

// ---------------------------------------------------------------------------
// helpers
// ---------------------------------------------------------------------------
__device__ __forceinline__ uint32_t pack_f16(float lo, float hi) {
    uint32_t w;
    asm("cvt.rn.f16x2.f32 %0, %1, %2;" : "=r"(w) : "f"(hi), "f"(lo));
    return w;
}
__device__ __forceinline__ void unpack_f16(uint32_t w, float& lo, float& hi) {
    __half2 h = *(__half2*)&w;
    lo = __low2float(h);
    hi = __high2float(h);
}
__device__ __forceinline__ void mma_f16(float c[4], const uint32_t a[4], const uint32_t b[2]) {
    asm volatile(
        "mma.sync.aligned.m16n8k16.row.col.f32.f16.f16.f32 "
        "{%0,%1,%2,%3}, {%4,%5,%6,%7}, {%8,%9}, {%0,%1,%2,%3};\n"
        : "+f"(c[0]), "+f"(c[1]), "+f"(c[2]), "+f"(c[3])
        : "r"(a[0]), "r"(a[1]), "r"(a[2]), "r"(a[3]), "r"(b[0]), "r"(b[1]));
}
__device__ __forceinline__ void ldsm4(uint32_t f[4], uint32_t addr) {
    asm volatile("ldmatrix.sync.aligned.m8n8.x4.shared.b16 {%0,%1,%2,%3}, [%4];"
                 : "=r"(f[0]), "=r"(f[1]), "=r"(f[2]), "=r"(f[3]) : "r"(addr));
}
__device__ __forceinline__ void cp16(uint32_t dst, const void* src) {
    asm volatile("cp.async.cg.shared.global [%0], [%1], 16;" :: "r"(dst), "l"(src));
}
__device__ __forceinline__ void cp_commit() {
    asm volatile("cp.async.commit_group;" ::: "memory");
}
template <int N>
__device__ __forceinline__ void cp_wait() {
    asm volatile("cp.async.wait_group %0;" :: "n"(N) : "memory");
}

// ---------------------------------------------------------------------------
// producers
// ---------------------------------------------------------------------------
__global__ void split_kernel(const float* __restrict__ in,
                             __half* __restrict__ oh, __half* __restrict__ ol)
{
    int idx = blockIdx.x * blockDim.x + threadIdx.x;
    float v = in[idx];
    __half h = __float2half_rn(v);
    oh[idx] = h;
    ol[idx] = __float2half_rn(v - __half2float(h));
}

__global__ void transpose_split_kernel(const float* __restrict__ in,
                                       __half* __restrict__ oh, __half* __restrict__ ol,
                                       int R, int C, long long sIn, long long sOut)
{
    __shared__ float t[32][33];
    in += (long long)blockIdx.z * sIn;
    oh += (long long)blockIdx.z * sOut;
    ol += (long long)blockIdx.z * sOut;
    int r0 = blockIdx.y * 32, c0 = blockIdx.x * 32;
    int tx = threadIdx.x, ty = threadIdx.y;
#pragma unroll
    for (int i = 0; i < 4; i++)
        t[ty + 8 * i][tx] = in[(long long)(r0 + ty + 8 * i) * C + c0 + tx];
    __syncthreads();
#pragma unroll
    for (int i = 0; i < 4; i++) {
        float v = t[tx][ty + 8 * i];
        __half h = __float2half_rn(v);
        long long o = (long long)(c0 + ty + 8 * i) * R + r0 + tx;
        oh[o] = h;
        ol[o] = __float2half_rn(v - __half2float(h));
    }
}

__global__ void rel_hidden_kernel(const float* __restrict__ relations,
                                  const float* __restrict__ w1,
                                  const float* __restrict__ b1,
                                  __half* __restrict__ oh, __half* __restrict__ ol)
{
    int idx = blockIdx.x * blockDim.x + threadIdx.x;
    int s = idx >> 10;
    int d = idx & (DM - 1);
    float v = b1[d];
    v = fmaf(relations[s * 4 + 0], w1[0 * DM + d], v);
    v = fmaf(relations[s * 4 + 1], w1[1 * DM + d], v);
    v = fmaf(relations[s * 4 + 2], w1[2 * DM + d], v);
    v = fmaf(relations[s * 4 + 3], w1[3 * DM + d], v);
    v = fmaxf(v, 0.0f);
    __half h = __float2half_rn(v);
    oh[idx] = h;
    ol[idx] = __float2half_rn(v - __half2float(h));
}

// split-K=2 reduction for GEMM7: out = part0 + part1 + bias
__global__ void reduce2_kernel(const float* __restrict__ part,
                               const float* __restrict__ bias,
                               float* __restrict__ out)
{
    int i = blockIdx.x * 256 + threadIdx.x;       // float4 index over SQ*DM/4
    const long long P = (long long)SQ * DM;
    float4 a = *(const float4*)&part[(long long)i * 4];
    float4 b = *(const float4*)&part[P + (long long)i * 4];
    int col = (i * 4) & (DM - 1);
    float4 bb = *(const float4*)&bias[col];
    float4 o;
    o.x = a.x + b.x + bb.x;
    o.y = a.y + b.y + bb.y;
    o.z = a.z + b.z + bb.z;
    o.w = a.w + b.w + bb.w;
    *(float4*)&out[(long long)i * 4] = o;
}

// ---------------------------------------------------------------------------
// Pre-split fp16 3-term NT GEMM (round-13 proven version):
//   C[M,N] = (Ah+Al)[M,K] @ (Bh+Bl)[N,K]^T    terms: Ah*Bl + Ah*Bh + Al*Bh
// CTA tile 128x128, BK=32, 256 threads, warp tile 64x32 (4x4 m16n8k16).
// ---------------------------------------------------------------------------
#define TILE_B 10240            // 128 * 80 bytes
#define STAGE_B (4 * TILE_B)    // 40960

template <int EPI_SPLIT>
__global__ __launch_bounds__(256, 2)
void gemm_pre(const __half* __restrict__ Ah, const __half* __restrict__ Al,
              const __half* __restrict__ Bh, const __half* __restrict__ Bl,
              float* __restrict__ Cf, __half* __restrict__ Ch, __half* __restrict__ Cl,
              const float* __restrict__ bias,
              int K, int lda, int ldb, int ldc,
              long long sAb, long long sBb, long long sCb)
{
    extern __shared__ char sm[];
    const uint32_t sbase = (uint32_t)__cvta_generic_to_shared(sm);

    const int tid  = threadIdx.x;
    const int lane = tid & 31;
    const int w    = tid >> 5;
    const int q    = lane >> 2;
    const int r    = lane & 3;
    const int wm   = (w & 1) * 64;
    const int wn   = (w >> 1) * 32;

    const long long z = blockIdx.z;
    Ah += z * sAb;  Al += z * sAb;
    Bh += z * sBb;  Bl += z * sBb;
    if (EPI_SPLIT) { Ch += z * sCb; Cl += z * sCb; }
    else           { Cf += z * sCb; }
    const int bm = blockIdx.y * 128;
    const int bn = blockIdx.x * 128;

    const int r8 = lane & 7, g = lane >> 3;
    const uint32_t frag = (uint32_t)(((r8 + 8 * (g & 1)) * 20 + 4 * (g >> 1)) * 4);
    const uint32_t aoff = frag + (uint32_t)wm * 80;
    const uint32_t boff = frag + (uint32_t)wn * 80;

    auto stage_load = [&](int st, int k0) {
        uint32_t s0 = sbase + st * STAGE_B;
#pragma unroll
        for (int i = 0; i < 8; i++) {
            int c = tid + 256 * i;
            int t = c >> 9;
            int within = c & 511;
            int row = within >> 2;
            int seg = within & 3;
            uint32_t dst = s0 + t * TILE_B + row * 80 + seg * 16;
            const __half* src = (t < 2) ? ((t == 0) ? Ah : Al)
                                        : ((t == 2) ? Bh : Bl);
            int rb = (t < 2) ? bm : bn;
            int ld = (t < 2) ? lda : ldb;
            cp16(dst, src + (long long)(rb + row) * ld + k0 + seg * 8);
        }
    };

    float acc[4][4][4] = {};

    auto compute = [&](int st) {
        uint32_t s0 = sbase + st * STAGE_B;
#pragma unroll
        for (int k16 = 0; k16 < 2; k16++) {
            const uint32_t ko = k16 * 32;
            uint32_t af[4][4], bp[2][4];
#pragma unroll
            for (int mi = 0; mi < 4; mi++) ldsm4(af[mi], s0 + aoff + mi * 1280 + ko);
#pragma unroll
            for (int p = 0; p < 2; p++)    ldsm4(bp[p], s0 + 3 * TILE_B + boff + p * 1280 + ko);
#pragma unroll
            for (int mi = 0; mi < 4; mi++)
#pragma unroll
                for (int ni = 0; ni < 4; ni++) {
                    uint32_t b2[2] = { bp[ni >> 1][ni & 1], bp[ni >> 1][2 + (ni & 1)] };
                    mma_f16(acc[mi][ni], af[mi], b2);
                }
#pragma unroll
            for (int p = 0; p < 2; p++)    ldsm4(bp[p], s0 + 2 * TILE_B + boff + p * 1280 + ko);
#pragma unroll
            for (int mi = 0; mi < 4; mi++)
#pragma unroll
                for (int ni = 0; ni < 4; ni++) {
                    uint32_t b2[2] = { bp[ni >> 1][ni & 1], bp[ni >> 1][2 + (ni & 1)] };
                    mma_f16(acc[mi][ni], af[mi], b2);
                }
#pragma unroll
            for (int mi = 0; mi < 4; mi++) ldsm4(af[mi], s0 + TILE_B + aoff + mi * 1280 + ko);
#pragma unroll
            for (int mi = 0; mi < 4; mi++)
#pragma unroll
                for (int ni = 0; ni < 4; ni++) {
                    uint32_t b2[2] = { bp[ni >> 1][ni & 1], bp[ni >> 1][2 + (ni & 1)] };
                    mma_f16(acc[mi][ni], af[mi], b2);
                }
        }
    };

    const int iters = K >> 5;

    stage_load(0, 0);
    cp_commit();

    for (int it = 0; it < iters; ++it) {
        if (it + 1 < iters) {
            stage_load((it + 1) & 1, (it + 1) << 5);
            cp_commit();
            cp_wait<1>();
        } else {
            cp_wait<0>();
        }
        __syncthreads();
        compute(it & 1);
        __syncthreads();
    }

#pragma unroll
    for (int mi = 0; mi < 4; mi++) {
#pragma unroll
        for (int ni = 0; ni < 4; ni++) {
            int row = bm + wm + mi * 16 + q;
            int col = bn + wn + ni * 8 + 2 * r;
            float c0 = acc[mi][ni][0], c1 = acc[mi][ni][1];
            float c2 = acc[mi][ni][2], c3 = acc[mi][ni][3];
            if (bias) {
                float2 bb = *(const float2*)&bias[col];
                c0 += bb.x; c1 += bb.y;
                c2 += bb.x; c3 += bb.y;
            }
            if (EPI_SPLIT) {
                long long o0 = ((long long)row * ldc + col) >> 1;
                long long o1 = ((long long)(row + 8) * ldc + col) >> 1;
                uint32_t hw0 = pack_f16(c0, c1);
                float h0, h1; unpack_f16(hw0, h0, h1);
                ((uint32_t*)Ch)[o0] = hw0;
                ((uint32_t*)Cl)[o0] = pack_f16(c0 - h0, c1 - h1);
                uint32_t hw1 = pack_f16(c2, c3);
                unpack_f16(hw1, h0, h1);
                ((uint32_t*)Ch)[o1] = hw1;
                ((uint32_t*)Cl)[o1] = pack_f16(c2 - h0, c3 - h1);
            } else {
                *(float2*)&Cf[(long long)row * ldc + col]       = make_float2(c0, c1);
                *(float2*)&Cf[(long long)(row + 8) * ldc + col] = make_float2(c2, c3);
            }
        }
    }
}

// ---------------------------------------------------------------------------
// Fused softmax + sparse context gather.
// One block (256 thr) per (h,s) logits row. Full fp32 softmax (normalization
// over all 2048), then entries with p > 1e-9 are compacted (deterministic
// ballot-prefix order) and context[s, h*D+:] = sum_i p_i * x[t_i,:] is
// computed in fp32 and written as fp16 h/l split. Dropped mass <= 2e-6.
// ---------------------------------------------------------------------------
__global__ __launch_bounds__(256)
void softmax_gather_kernel(const float* __restrict__ logits,
                           const float* __restrict__ x,
                           __half* __restrict__ ctx_h, __half* __restrict__ ctx_l)
{
    const long long rbase = (long long)blockIdx.x * SQ;
    const int h = blockIdx.x >> 11;          // row / SQ
    const int s = blockIdx.x & (SQ - 1);
    const float* row = logits + rbase;
    const int t = threadIdx.x;
    const int lane = t & 31, w = t >> 5;

    __shared__ float redm[8], reds[8];
    __shared__ int   wbase[8];
    __shared__ int   s_idx[SQ];
    __shared__ float s_p[SQ];
    __shared__ int   s_cnt;

    float4 a = *(const float4*)&row[t * 8];
    float4 b = *(const float4*)&row[t * 8 + 4];

    float m = fmaxf(fmaxf(fmaxf(a.x, a.y), fmaxf(a.z, a.w)),
                    fmaxf(fmaxf(b.x, b.y), fmaxf(b.z, b.w)));
#pragma unroll
    for (int o = 16; o > 0; o >>= 1) m = fmaxf(m, __shfl_xor_sync(0xffffffffu, m, o));
    if (lane == 0) redm[w] = m;
    __syncthreads();
    float mm = redm[0];
#pragma unroll
    for (int i = 1; i < 8; i++) mm = fmaxf(mm, redm[i]);

    float p[8];
    p[0] = __expf(a.x - mm); p[1] = __expf(a.y - mm);
    p[2] = __expf(a.z - mm); p[3] = __expf(a.w - mm);
    p[4] = __expf(b.x - mm); p[5] = __expf(b.y - mm);
    p[6] = __expf(b.z - mm); p[7] = __expf(b.w - mm);

    float ssum = (p[0] + p[1]) + (p[2] + p[3]) + (p[4] + p[5]) + (p[6] + p[7]);
#pragma unroll
    for (int o = 16; o > 0; o >>= 1) ssum += __shfl_xor_sync(0xffffffffu, ssum, o);
    if (lane == 0) reds[w] = ssum;
    __syncthreads();
    float tot = reds[0];
#pragma unroll
    for (int i = 1; i < 8; i++) tot += reds[i];
    const float inv = 1.0f / tot;

    // deterministic compaction of p*inv > 1e-9
    const float thr = 1e-9f;
    uint32_t mask[8];
    int wcnt = 0;
#pragma unroll
    for (int j = 0; j < 8; j++) {
        p[j] *= inv;
        mask[j] = __ballot_sync(0xffffffffu, p[j] > thr);
        wcnt += __popc(mask[j]);
    }
    if (lane == 0) wbase[w] = wcnt;
    __syncthreads();
    int base = 0;
#pragma unroll
    for (int i = 0; i < 8; i++) {
        if (i < w) base += wbase[i];
    }
    if (t == 0) {
        int c = 0;
#pragma unroll
        for (int i = 0; i < 8; i++) c += wbase[i];
        s_cnt = c;
    }
    {
        int off = 0;
        uint32_t below = (1u << lane) - 1u;
#pragma unroll
        for (int j = 0; j < 8; j++) {
            if (p[j] > thr) {
                int pos = base + off + __popc(mask[j] & below);
                s_idx[pos] = t * 8 + j;
                s_p[pos] = p[j];
            }
            off += __popc(mask[j]);
        }
    }
    __syncthreads();

    // gather: each thread computes 4 dims of context row
    const int c = s_cnt;
    float acc0 = 0.f, acc1 = 0.f, acc2 = 0.f, acc3 = 0.f;
    for (int i = 0; i < c; i++) {
        float pi = s_p[i];
        const float4 xv = *(const float4*)&x[(long long)s_idx[i] * DM + t * 4];
        acc0 = fmaf(pi, xv.x, acc0);
        acc1 = fmaf(pi, xv.y, acc1);
        acc2 = fmaf(pi, xv.z, acc2);
        acc3 = fmaf(pi, xv.w, acc3);
    }

    long long o = (long long)s * (NH * DM) + h * DM + t * 4;
    uint32_t hw0 = pack_f16(acc0, acc1);
    uint32_t hw1 = pack_f16(acc2, acc3);
    float h0, h1, h2, h3;
    unpack_f16(hw0, h0, h1);
    unpack_f16(hw1, h2, h3);
    *(uint2*)&((uint32_t*)ctx_h)[o >> 1] = make_uint2(hw0, hw1);
    *(uint2*)&((uint32_t*)ctx_l)[o >> 1] =
        make_uint2(pack_f16(acc0 - h0, acc1 - h1), pack_f16(acc2 - h2, acc3 - h3));
}

// ---------------------------------------------------------------------------
// Launch
// ---------------------------------------------------------------------------
extern "C" void kernel_launch(void* const* d_in, const int* in_sizes, int n_in,
                              void* d_out, int out_size)
{
    const float* x         = (const float*)d_in[0];
    const float* relations = (const float*)d_in[1];
    const float* re_w1     = (const float*)d_in[2];
    const float* re_b1     = (const float*)d_in[3];
    const float* re_w2     = (const float*)d_in[4];
    const float* re_b2     = (const float*)d_in[5];
    const float* attn_w    = (const float*)d_in[6];
    const float* out_w     = (const float*)d_in[7];
    const float* out_b     = (const float*)d_in[8];
    float* out = (float*)d_out;

    __half *hidden_h, *hidden_l, *rel_h, *rel_l, *x_h, *x_l;
    __half *scores_h, *scores_l, *context_h, *context_l;
    __half *rew2T_h, *rew2T_l, *attnwT_h, *attnwT_l, *outwT_h, *outwT_l;
    float *logits, *part;
    cudaGetSymbolAddress((void**)&hidden_h,  g_hidden_h);
    cudaGetSymbolAddress((void**)&hidden_l,  g_hidden_l);
    cudaGetSymbolAddress((void**)&rel_h,     g_rel_h);
    cudaGetSymbolAddress((void**)&rel_l,     g_rel_l);
    cudaGetSymbolAddress((void**)&x_h,       g_x_h);
    cudaGetSymbolAddress((void**)&x_l,       g_x_l);
    cudaGetSymbolAddress((void**)&scores_h,  g_scores_h);
    cudaGetSymbolAddress((void**)&scores_l,  g_scores_l);
    cudaGetSymbolAddress((void**)&logits,    g_logits);
    cudaGetSymbolAddress((void**)&context_h, g_context_h);
    cudaGetSymbolAddress((void**)&context_l, g_context_l);
    cudaGetSymbolAddress((void**)&rew2T_h,   g_rew2T_h);
    cudaGetSymbolAddress((void**)&rew2T_l,   g_rew2T_l);
    cudaGetSymbolAddress((void**)&attnwT_h,  g_attnwT_h);
    cudaGetSymbolAddress((void**)&attnwT_l,  g_attnwT_l);
    cudaGetSymbolAddress((void**)&outwT_h,   g_outwT_h);
    cudaGetSymbolAddress((void**)&outwT_l,   g_outwT_l);
    cudaGetSymbolAddress((void**)&part,      g_part);

    const int smemB = 2 * STAGE_B;   // 81920
    cudaFuncSetAttribute(gemm_pre<0>, cudaFuncAttributeMaxDynamicSharedMemorySize, smemB);
    cudaFuncSetAttribute(gemm_pre<1>, cudaFuncAttributeMaxDynamicSharedMemorySize, smemB);

    // 0) one-time splits / transposed splits
    transpose_split_kernel<<<dim3(32, 32, 1), dim3(32, 8)>>>(re_w2, rew2T_h, rew2T_l, DM, DM, 0, 0);
    transpose_split_kernel<<<dim3(32, 32, NH), dim3(32, 8)>>>(attn_w, attnwT_h, attnwT_l, DM, DM,
                                                              (long long)DM * DM, (long long)DM * DM);
    transpose_split_kernel<<<dim3(32, 256, 1), dim3(32, 8)>>>(out_w, outwT_h, outwT_l, NH * DM, DM, 0, 0);
    split_kernel<<<(SQ * DM) / 256, 256>>>(x, x_h, x_l);

    // 1) hidden = relu(relations @ re_w1 + b1), split
    rel_hidden_kernel<<<(SQ * DM) / 256, 256>>>(relations, re_w1, re_b1, hidden_h, hidden_l);

    // 2) rel = hidden @ re_w2 + b2  -> split
    gemm_pre<1><<<dim3(8, 16, 1), 256, smemB>>>(
        hidden_h, hidden_l, rew2T_h, rew2T_l, nullptr, rel_h, rel_l, re_b2,
        DM, DM, DM, DM, 0, 0, 0);

    // 3) scores[h] = x @ attn_w[h] -> split; flat [16384][1024]
    gemm_pre<1><<<dim3(8, 16, NH), 256, smemB>>>(
        x_h, x_l, attnwT_h, attnwT_l, nullptr, scores_h, scores_l, nullptr,
        DM, DM, DM, DM, 0, (long long)DM * DM, (long long)SQ * DM);

    // 4) logits[h] = rel @ K_h^T -> fp32; key row t = scores flat row (t*8+h)
    gemm_pre<0><<<dim3(16, 16, NH), 256, smemB>>>(
        rel_h, rel_l, scores_h, scores_l, logits, nullptr, nullptr, nullptr,
        DM, DM, NH * DM, SQ, 0, (long long)DM, (long long)SQ * SQ);

    // 5+6) softmax + sparse gather: context = attn @ x  (fp32), split to h/l
    softmax_gather_kernel<<<NH * SQ, 256>>>(logits, x, context_h, context_l);

    // 7) out = context @ out_w + out_b: split-K=2, partials fp32, then reduce
    gemm_pre<0><<<dim3(8, 16, 2), 256, smemB>>>(
        context_h, context_l, outwT_h, outwT_l, part, nullptr, nullptr, nullptr,
        NH * DM / 2, NH * DM, NH * DM, DM,
        (long long)(NH * DM / 2), (long long)(NH * DM / 2), (long long)SQ * DM);
    reduce2_kernel<<<(SQ * DM / 4) / 256, 256>>>(part, out_b, out);

    (void)in_sizes; (void)n_in; (void)out_size;
}